// round 10
// baseline (speedup 1.0000x reference)
#include <cuda_runtime.h>
#include <cuda_fp16.h>
#include <cstdint>

#define NG 2048
static const int NMAX = 100000;
static const int EMAX = 1250000;

// Per-branch scratch (device globals — no allocations allowed)
__device__ __align__(16) __half g_hs_c[NMAX * 64];   // gemm out (scaled, fp16)
__device__ __align__(16) __half g_hB_c[NMAX * 64];   // conv out (fp16)
__device__ __align__(16) __half g_hs_s[NMAX * 32];
__device__ __align__(16) __half g_hB_s[NMAX * 32];
__device__ float g_dinv_c[NMAX];
__device__ float g_dinv_s[NMAX];
__device__ int   g_cnt_c[NMAX];
__device__ int   g_cnt_s[NMAX];
__device__ int   g_start_c[NMAX];
__device__ int   g_start_s[NMAX];
__device__ int   g_cursor_c[NMAX];
__device__ int   g_cursor_s[NMAX];
__device__ int   g_perm_c[EMAX];
__device__ int   g_perm_s[EMAX];
__device__ int   g_tot_c;
__device__ int   g_tot_s;

// ---------------------------------------------------------------------------
// Merged zero: both branches' cnt arrays + totals.
__global__ void k_zero2(int* cntc, int nc, int* cnts, int ns, int* totc, int* tots) {
    int i = blockIdx.x * blockDim.x + threadIdx.x;
    if (i < nc) cntc[i] = 0;
    if (i < ns) cnts[i] = 0;
    if (i == 0) { *totc = 0; *tots = 0; }
}

// Merged count: blocks [0, half) -> c, [half, grid) -> s.
__global__ void k_count2(const int* __restrict__ dstc, int Ec,
                         const int* __restrict__ dsts, int Es,
                         int* cntc, int* cnts, int halfBlocks) {
    bool isC = blockIdx.x < halfBlocks;
    const int* dst = isC ? dstc : dsts;
    int* cnt = isC ? cntc : cnts;
    int E = isC ? Ec : Es;
    int b = isC ? blockIdx.x : blockIdx.x - halfBlocks;
    int nb = isC ? halfBlocks : gridDim.x - halfBlocks;
    int stride = nb * blockDim.x;
    for (int i = b * blockDim.x + threadIdx.x; i < E; i += stride)
        atomicAdd(&cnt[dst[i]], 1);
}

// Merged offsets: warp-aggregated segment assignment (arbitrary segment order)
// + dinv. Blocks [0, nbC) -> c, rest -> s. Warps never straddle branches.
__global__ void k_offsets2(const int* __restrict__ cntc, int* startc, int* cursorc,
                           float* dinvc, int* totc, int nc, int nbC,
                           const int* __restrict__ cnts, int* starts, int* cursors,
                           float* dinvs, int* tots, int ns) {
    bool isC = blockIdx.x < (unsigned)nbC;
    const int* cnt = isC ? cntc : cnts;
    int* start = isC ? startc : starts;
    int* cursor = isC ? cursorc : cursors;
    float* dinv = isC ? dinvc : dinvs;
    int* tot = isC ? totc : tots;
    int n = isC ? nc : ns;
    int b = isC ? blockIdx.x : blockIdx.x - nbC;

    int i = b * blockDim.x + threadIdx.x;
    int lane = threadIdx.x & 31;
    int c = (i < n) ? cnt[i] : 0;
    int inc = c;
#pragma unroll
    for (int off = 1; off < 32; off <<= 1) {
        int u = __shfl_up_sync(0xffffffffu, inc, off);
        if (lane >= off) inc += u;
    }
    int wtot = __shfl_sync(0xffffffffu, inc, 31);
    int base = 0;
    if (lane == 31) base = atomicAdd(tot, wtot);
    base = __shfl_sync(0xffffffffu, base, 31);
    if (i < n) {
        int st = base + inc - c;
        start[i] = st;
        cursor[i] = st;
        dinv[i] = rsqrtf(1.0f + (float)c);
    }
}

__global__ void k_build(const int* __restrict__ src, const int* __restrict__ dst,
                        int* cursor, int* perm, int E) {
    int stride = gridDim.x * blockDim.x;
    for (int i = blockIdx.x * blockDim.x + threadIdx.x; i < E; i += stride) {
        int p = atomicAdd(&cursor[dst[i]], 1);
        perm[p] = src[i];
    }
}

// ---------------------------------------------------------------------------
__device__ __forceinline__ __half2 load_h2(const float* p, bool relu) {
    float2 v = *(const float2*)p;
    if (relu) { v.x = fmaxf(v.x, 0.0f); v.y = fmaxf(v.y, 0.0f); }
    return __floats2half2_rn(v.x, v.y);
}
__device__ __forceinline__ __half2 load_h2(const __half* p, bool relu) {
    __half2 v = *(const __half2*)p;
    if (relu) v = __hmax2(v, __floats2half2_rn(0.0f, 0.0f));
    return v;
}

// ---------------------------------------------------------------------------
// Tensor-core GEMM: hs(half) = (act(x) @ W) * dinv[row]
template <int FIN, int FOUT, bool RELU, typename TIN>
__global__ void k_gemm_mma(const TIN* __restrict__ x, const float* __restrict__ W,
                           const float* __restrict__ dinv, __half* __restrict__ h, int N) {
    constexpr int KC = FIN / 16;
    constexpr int NT = FOUT / 8;
    constexpr int ASTR = FIN + 8;
    constexpr int BSTR = FOUT + 8;
    __shared__ __half As[128 * ASTR];
    __shared__ __half Bs[FIN * BSTR];
    int tid = threadIdx.x;
    int base = blockIdx.x * 128;

    for (int i = tid; i < FIN * FOUT; i += 256) {
        int r = i / FOUT, cc = i % FOUT;
        Bs[r * BSTR + cc] = __float2half_rn(W[i]);
    }
    constexpr int PAIRS = 128 * FIN / 2;
    for (int p = tid; p < PAIRS; p += 256) {
        int r = p / (FIN / 2), cp = p % (FIN / 2);
        int grow = base + r;
        __half2 hv = (grow < N) ? load_h2(&x[(long long)grow * FIN + cp * 2], RELU)
                                : __floats2half2_rn(0.0f, 0.0f);
        *(__half2*)&As[r * ASTR + cp * 2] = hv;
    }
    __syncthreads();

    int warp = tid >> 5, lane = tid & 31;
    float acc[NT][4];
#pragma unroll
    for (int nt = 0; nt < NT; nt++)
#pragma unroll
        for (int j = 0; j < 4; j++) acc[nt][j] = 0.0f;

    uint32_t a_addr0 = (uint32_t)__cvta_generic_to_shared(
        &As[(warp * 16 + (lane & 15)) * ASTR + (lane >> 4) * 8]);
    uint32_t b_row = (lane & 15);

#pragma unroll
    for (int kc = 0; kc < KC; kc++) {
        uint32_t a0, a1, a2, a3;
        uint32_t aa = a_addr0 + kc * 16 * 2;
        asm volatile("ldmatrix.sync.aligned.m8n8.x4.shared.b16 {%0,%1,%2,%3}, [%4];"
                     : "=r"(a0), "=r"(a1), "=r"(a2), "=r"(a3) : "r"(aa));
#pragma unroll
        for (int nt = 0; nt < NT; nt++) {
            uint32_t b0, b1;
            uint32_t ba = (uint32_t)__cvta_generic_to_shared(
                &Bs[(kc * 16 + b_row) * BSTR + nt * 8]);
            asm volatile("ldmatrix.sync.aligned.m8n8.x2.trans.shared.b16 {%0,%1}, [%2];"
                         : "=r"(b0), "=r"(b1) : "r"(ba));
            asm volatile(
                "mma.sync.aligned.m16n8k16.row.col.f32.f16.f16.f32 "
                "{%0,%1,%2,%3}, {%4,%5,%6,%7}, {%8,%9}, {%0,%1,%2,%3};"
                : "+f"(acc[nt][0]), "+f"(acc[nt][1]), "+f"(acc[nt][2]), "+f"(acc[nt][3])
                : "r"(a0), "r"(a1), "r"(a2), "r"(a3), "r"(b0), "r"(b1));
        }
    }

    int r0 = base + warp * 16 + (lane >> 2);
    int r1 = r0 + 8;
    float d0 = (r0 < N) ? dinv[r0] : 0.0f;
    float d1 = (r1 < N) ? dinv[r1] : 0.0f;
    int colb = (lane & 3) * 2;
#pragma unroll
    for (int nt = 0; nt < NT; nt++) {
        int col = nt * 8 + colb;
        if (r0 < N)
            *(__half2*)&h[(long long)r0 * FOUT + col] =
                __floats2half2_rn(acc[nt][0] * d0, acc[nt][1] * d0);
        if (r1 < N)
            *(__half2*)&h[(long long)r1 * FOUT + col] =
                __floats2half2_rn(acc[nt][2] * d1, acc[nt][3] * d1);
    }
}

// ---------------------------------------------------------------------------
// CSR aggregation: out[d] = half( dinv[d]*(hs[d] + sum hs[src]) + b )
__global__ void k_agg64(const int* __restrict__ start, const int* __restrict__ cnt,
                        const int* __restrict__ perm,
                        const __half* __restrict__ hs, const float* __restrict__ dinv,
                        const float* __restrict__ b, __half* __restrict__ out, int N) {
    int warp = (blockIdx.x * blockDim.x + threadIdx.x) >> 5;
    if (warp >= N) return;
    int lane = threadIdx.x & 31;
    const __half2* H = (const __half2*)hs;
    float2 acc = __half22float2(H[(long long)warp * 32 + lane]);
    int lo = start[warp], hi = lo + cnt[warp];
    for (int base = lo; base < hi; base += 32) {
        int n = min(32, hi - base);
        int s = (lane < n) ? perm[base + lane] : 0;
        for (int j = 0; j < n; j++) {
            int sj = __shfl_sync(0xffffffffu, s, j);
            float2 v = __half22float2(H[(long long)sj * 32 + lane]);
            acc.x += v.x; acc.y += v.y;
        }
    }
    float d = dinv[warp];
    float2 bb = ((const float2*)b)[lane];
    ((__half2*)out)[(long long)warp * 32 + lane] =
        __floats2half2_rn(acc.x * d + bb.x, acc.y * d + bb.y);
}

__global__ void k_agg32(const int* __restrict__ start, const int* __restrict__ cnt,
                        const int* __restrict__ perm,
                        const __half* __restrict__ hs, const float* __restrict__ dinv,
                        const float* __restrict__ b, __half* __restrict__ out, int N) {
    int t = blockIdx.x * blockDim.x + threadIdx.x;
    int node = t >> 4;
    if (node >= N) return;
    int sub = t & 15;
    const __half2* H = (const __half2*)hs;
    float2 acc = __half22float2(H[(long long)node * 16 + sub]);
    int lo = start[node], hi = lo + cnt[node];
    for (int base = lo; base < hi; base += 16) {
        int n = min(16, hi - base);
        int s = (sub < n) ? perm[base + sub] : 0;
        for (int j = 0; j < n; j++) {
            int sj = __shfl_sync(0xffffffffu, s, j, 16);
            float2 v = __half22float2(H[(long long)sj * 16 + sub]);
            acc.x += v.x; acc.y += v.y;
        }
    }
    float d = dinv[node];
    float2 bb = ((const float2*)b)[sub];
    ((__half2*)out)[(long long)node * 16 + sub] =
        __floats2half2_rn(acc.x * d + bb.x, acc.y * d + bb.y);
}

// ---------------------------------------------------------------------------
// Fused head: pooling (both branches) + dense MLP. GPB graphs per block.
// Wd staged in dynamic smem (98,304B) so its L2 traffic is read NG/GPB times
// instead of NG times.
#define GPB 8
__global__ void k_head(const __half* __restrict__ xc, const int* __restrict__ c_batch, int Nc,
                       const __half* __restrict__ xs, const int* __restrict__ s_batch, int Ns,
                       const float* __restrict__ Wd, const float* __restrict__ bd,
                       const float* __restrict__ Wo, const float* __restrict__ bo,
                       float* __restrict__ embed, float* __restrict__ out) {
    extern __shared__ float sm[];
    float* Wds = sm;             // 192*128
    float* Wos = Wds + 192 * 128;  // 128
    float* es  = Wos + 128;        // 192
    float* red = es + 192;         // 4
    int tid = threadIdx.x;

    for (int i = tid; i < 192 * 128; i += 128) Wds[i] = Wd[i];
    if (tid < 128) Wos[tid] = Wo[tid];
    __syncthreads();

    for (int gi = 0; gi < GPB; gi++) {
        int g = blockIdx.x * GPB + gi;
        // ---- pooling ----
        if (tid < 96) {
            bool isC = tid < 64;
            const __half* x = isC ? xc : xs;
            const int* batch = isC ? c_batch : s_batch;
            int N = isC ? Nc : Ns;
            int F = isC ? 64 : 32;
            int j = isC ? tid : tid - 64;
            int lo = 0, hi = N;
            while (lo < hi) { int m = (lo + hi) >> 1; if (batch[m] < g) lo = m + 1; else hi = m; }
            int lo2 = lo, hi2 = N;
            while (lo2 < hi2) { int m = (lo2 + hi2) >> 1; if (batch[m] < g + 1) lo2 = m + 1; else hi2 = m; }
            float mx = 0.0f, sum = 0.0f;
            for (int r = lo; r < lo2; r++) {
                float v = fmaxf(__half2float(x[(long long)r * F + j]), 0.0f);
                mx = fmaxf(mx, v);
                sum += v;
            }
            float mean = sum / fmaxf((float)(lo2 - lo), 1.0f);
            int mxcol = isC ? j : 128 + j;
            int mncol = isC ? 64 + j : 160 + j;
            es[mxcol] = mx;
            es[mncol] = mean;
            float* erow = &embed[(long long)g * 192];
            erow[mxcol] = mx;
            erow[mncol] = mean;
        }
        __syncthreads();
        // ---- dense MLP ----
        float a = bd[tid];
#pragma unroll 8
        for (int k = 0; k < 192; k++) a += es[k] * Wds[k * 128 + tid];
        a = fmaxf(a, 0.0f);
        float v = a * Wos[tid];
#pragma unroll
        for (int o = 16; o > 0; o >>= 1) v += __shfl_down_sync(0xffffffffu, v, o);
        if ((tid & 31) == 0) red[tid >> 5] = v;
        __syncthreads();
        if (tid == 0) out[g] = red[0] + red[1] + red[2] + red[3] + bo[0];
        __syncthreads();
    }
}

// ---------------------------------------------------------------------------
extern "C" void kernel_launch(void* const* d_in, const int* in_sizes, int n_in,
                              void* d_out, int out_size) {
    const float* c       = (const float*)d_in[0];
    const int*   c_edge  = (const int*)d_in[1];
    const int*   c_batch = (const int*)d_in[2];
    const float* s       = (const float*)d_in[3];
    const int*   s_edge  = (const int*)d_in[4];
    const int*   s_batch = (const int*)d_in[5];
    const float* Wc0 = (const float*)d_in[6],  *bc0 = (const float*)d_in[7];
    const float* Wc1 = (const float*)d_in[8],  *bc1 = (const float*)d_in[9];
    const float* Wc2 = (const float*)d_in[10], *bc2 = (const float*)d_in[11];
    const float* Ws0 = (const float*)d_in[12], *bs0 = (const float*)d_in[13];
    const float* Ws1 = (const float*)d_in[14], *bs1 = (const float*)d_in[15];
    const float* Ws2 = (const float*)d_in[16], *bs2 = (const float*)d_in[17];
    const float* Wd  = (const float*)d_in[18], *bd  = (const float*)d_in[19];
    const float* Wo  = (const float*)d_in[20], *bo  = (const float*)d_in[21];

    int Nc = in_sizes[0] / 64;
    int Ec = in_sizes[1] / 2;
    int Ns = in_sizes[3] / 64;
    int Es = in_sizes[4] / 2;

    float* out   = (float*)d_out;
    float* embed = out + NG;  // [NG, 192]

    __half *hs_c, *hB_c, *hs_s, *hB_s;
    float *dinv_c, *dinv_s;
    int *cnt_c, *cnt_s, *start_c, *start_s, *cursor_c, *cursor_s;
    int *perm_c, *perm_s, *tot_c, *tot_s;
    cudaGetSymbolAddress((void**)&hs_c, g_hs_c);
    cudaGetSymbolAddress((void**)&hB_c, g_hB_c);
    cudaGetSymbolAddress((void**)&hs_s, g_hs_s);
    cudaGetSymbolAddress((void**)&hB_s, g_hB_s);
    cudaGetSymbolAddress((void**)&dinv_c, g_dinv_c);
    cudaGetSymbolAddress((void**)&dinv_s, g_dinv_s);
    cudaGetSymbolAddress((void**)&cnt_c, g_cnt_c);
    cudaGetSymbolAddress((void**)&cnt_s, g_cnt_s);
    cudaGetSymbolAddress((void**)&start_c, g_start_c);
    cudaGetSymbolAddress((void**)&start_s, g_start_s);
    cudaGetSymbolAddress((void**)&cursor_c, g_cursor_c);
    cudaGetSymbolAddress((void**)&cursor_s, g_cursor_s);
    cudaGetSymbolAddress((void**)&perm_c, g_perm_c);
    cudaGetSymbolAddress((void**)&perm_s, g_perm_s);
    cudaGetSymbolAddress((void**)&tot_c, g_tot_c);
    cudaGetSymbolAddress((void**)&tot_s, g_tot_s);

    static cudaStream_t s2 = nullptr, s3 = nullptr, s4 = nullptr;
    static cudaEvent_t evF = nullptr, evD = nullptr, evA = nullptr, evB = nullptr, evJ = nullptr;
    static bool tried = false;
    static int headSmemOK = 0;
    const int HEAD_SMEM = (192 * 128 + 128 + 192 + 4) * 4;
    if (!tried) {
        tried = true;
        bool ok = cudaStreamCreateWithFlags(&s2, cudaStreamNonBlocking) == cudaSuccess &&
                  cudaStreamCreateWithFlags(&s3, cudaStreamNonBlocking) == cudaSuccess &&
                  cudaStreamCreateWithFlags(&s4, cudaStreamNonBlocking) == cudaSuccess;
        if (ok) {
            cudaEventCreateWithFlags(&evF, cudaEventDisableTiming);
            cudaEventCreateWithFlags(&evD, cudaEventDisableTiming);
            cudaEventCreateWithFlags(&evA, cudaEventDisableTiming);
            cudaEventCreateWithFlags(&evB, cudaEventDisableTiming);
            cudaEventCreateWithFlags(&evJ, cudaEventDisableTiming);
        } else {
            s2 = s3 = s4 = nullptr;
        }
        headSmemOK = (cudaFuncSetAttribute(k_head,
                        cudaFuncAttributeMaxDynamicSharedMemorySize,
                        HEAD_SMEM) == cudaSuccess) ? 1 : 0;
    }
    bool fork = (s2 != nullptr);
    cudaStream_t st0 = 0;
    cudaStream_t stS = fork ? s2 : st0;
    cudaStream_t stA = fork ? s3 : st0;
    cudaStream_t stB = fork ? s4 : st0;

    const int T = 256;
    const int GS = 1184;

    // ---- merged CSR prep (both branches) on st0 ----
    int nmax = (Nc > Ns) ? Nc : Ns;
    int nbC = (Nc + T - 1) / T;
    int nbS = (Ns + T - 1) / T;
    k_zero2<<<(nmax + T - 1) / T, T, 0, st0>>>(cnt_c, Nc, cnt_s, Ns, tot_c, tot_s);
    k_count2<<<GS, T, 0, st0>>>(c_edge + Ec, Ec, s_edge + Es, Es, cnt_c, cnt_s, GS / 2);
    k_offsets2<<<nbC + nbS, T, 0, st0>>>(cnt_c, start_c, cursor_c, dinv_c, tot_c, Nc, nbC,
                                         cnt_s, start_s, cursor_s, dinv_s, tot_s, Ns);
    if (fork) cudaEventRecord(evD, st0);

    int mmaBc = (Nc + 127) / 128;
    int aggBc = (Nc * 32 + T - 1) / T;
    int mmaBs = (Ns + 127) / 128;
    int aggBs = (Ns * 16 + T - 1) / T;

    // gemm0's (need only dinv) on side streams, overlapping the builds
    if (fork) {
        cudaStreamWaitEvent(stA, evD, 0);
        k_gemm_mma<64, 64, false><<<mmaBc, 256, 0, stA>>>(c, Wc0, dinv_c, hs_c, Nc);
        cudaEventRecord(evA, stA);
        cudaStreamWaitEvent(stB, evD, 0);
        k_gemm_mma<64, 32, false><<<mmaBs, 256, 0, stB>>>(s, Ws0, dinv_s, hs_s, Ns);
        cudaEventRecord(evB, stB);
        cudaStreamWaitEvent(stS, evD, 0);
    }

    // ---- c branch chain on st0 ----
    k_build<<<GS, T, 0, st0>>>(c_edge, c_edge + Ec, cursor_c, perm_c, Ec);
    if (fork) cudaStreamWaitEvent(st0, evA, 0);
    else      k_gemm_mma<64, 64, false><<<mmaBc, 256, 0, st0>>>(c, Wc0, dinv_c, hs_c, Nc);
    k_agg64<<<aggBc, T, 0, st0>>>(start_c, cnt_c, perm_c, hs_c, dinv_c, bc0, hB_c, Nc);
    k_gemm_mma<64, 64, true><<<mmaBc, 256, 0, st0>>>(hB_c, Wc1, dinv_c, hs_c, Nc);
    k_agg64<<<aggBc, T, 0, st0>>>(start_c, cnt_c, perm_c, hs_c, dinv_c, bc1, hB_c, Nc);
    k_gemm_mma<64, 64, true><<<mmaBc, 256, 0, st0>>>(hB_c, Wc2, dinv_c, hs_c, Nc);
    k_agg64<<<aggBc, T, 0, st0>>>(start_c, cnt_c, perm_c, hs_c, dinv_c, bc2, hB_c, Nc);

    // ---- s branch chain on stS ----
    k_build<<<GS, T, 0, stS>>>(s_edge, s_edge + Es, cursor_s, perm_s, Es);
    if (fork) cudaStreamWaitEvent(stS, evB, 0);
    else      k_gemm_mma<64, 32, false><<<mmaBs, 256, 0, stS>>>(s, Ws0, dinv_s, hs_s, Ns);
    k_agg32<<<aggBs, T, 0, stS>>>(start_s, cnt_s, perm_s, hs_s, dinv_s, bs0, hB_s, Ns);
    k_gemm_mma<32, 32, true><<<mmaBs, 256, 0, stS>>>(hB_s, Ws1, dinv_s, hs_s, Ns);
    k_agg32<<<aggBs, T, 0, stS>>>(start_s, cnt_s, perm_s, hs_s, dinv_s, bs1, hB_s, Ns);
    k_gemm_mma<32, 32, true><<<mmaBs, 256, 0, stS>>>(hB_s, Ws2, dinv_s, hs_s, Ns);
    k_agg32<<<aggBs, T, 0, stS>>>(start_s, cnt_s, perm_s, hs_s, dinv_s, bs2, hB_s, Ns);

    if (fork) {
        cudaEventRecord(evJ, stS);
        cudaStreamWaitEvent(st0, evJ, 0);
    }

    // ---- fused head: pooling + dense ----
    const int HEAD_SMEM2 = (192 * 128 + 128 + 192 + 4) * 4;
    k_head<<<NG / GPB, 128, HEAD_SMEM2, st0>>>(hB_c, c_batch, Nc, hB_s, s_batch, Ns,
                                               Wd, bd, Wo, bo, embed, out);
}

// round 11
// speedup vs baseline: 1.1654x; 1.1654x over previous
#include <cuda_runtime.h>
#include <cuda_fp16.h>
#include <cstdint>

#define NG 2048
static const int NMAX = 100000;
static const int EMAX = 1250000;

// Per-branch scratch (device globals — no allocations allowed)
__device__ __align__(16) __half g_hs_c[NMAX * 64];   // gemm out (scaled, fp16)
__device__ __align__(16) __half g_hB_c[NMAX * 64];   // conv out (fp16)
__device__ __align__(16) __half g_hs_s[NMAX * 32];
__device__ __align__(16) __half g_hB_s[NMAX * 32];
__device__ float g_dinv_c[NMAX];
__device__ float g_dinv_s[NMAX];
__device__ int   g_cnt_c[NMAX];
__device__ int   g_cnt_s[NMAX];
__device__ int   g_start_c[NMAX];
__device__ int   g_start_s[NMAX];
__device__ int   g_cursor_c[NMAX];
__device__ int   g_cursor_s[NMAX];
__device__ int   g_perm_c[EMAX];
__device__ int   g_perm_s[EMAX];
__device__ int   g_tot_c;
__device__ int   g_tot_s;

// ---------------------------------------------------------------------------
__global__ void k_zero(int* cnt, int* tot, int n) {
    int i = blockIdx.x * blockDim.x + threadIdx.x;
    if (i < n) cnt[i] = 0;
    if (i == 0) *tot = 0;
}

__global__ void k_count(const int* __restrict__ dst, int E, int* cnt) {
    int stride = gridDim.x * blockDim.x;
    for (int i = blockIdx.x * blockDim.x + threadIdx.x; i < E; i += stride)
        atomicAdd(&cnt[dst[i]], 1);
}

// Warp-aggregated segment assignment + dinv.
__global__ void k_offsets(const int* __restrict__ cnt, int* start, int* cursor,
                          float* dinv, int* tot, int n) {
    int i = blockIdx.x * blockDim.x + threadIdx.x;
    int lane = threadIdx.x & 31;
    int c = (i < n) ? cnt[i] : 0;
    int inc = c;
#pragma unroll
    for (int off = 1; off < 32; off <<= 1) {
        int u = __shfl_up_sync(0xffffffffu, inc, off);
        if (lane >= off) inc += u;
    }
    int wtot = __shfl_sync(0xffffffffu, inc, 31);
    int base = 0;
    if (lane == 31) base = atomicAdd(tot, wtot);
    base = __shfl_sync(0xffffffffu, base, 31);
    if (i < n) {
        int st = base + inc - c;
        start[i] = st;
        cursor[i] = st;
        dinv[i] = rsqrtf(1.0f + (float)c);
    }
}

__global__ void k_build(const int* __restrict__ src, const int* __restrict__ dst,
                        int* cursor, int* perm, int E) {
    int stride = gridDim.x * blockDim.x;
    for (int i = blockIdx.x * blockDim.x + threadIdx.x; i < E; i += stride) {
        int p = atomicAdd(&cursor[dst[i]], 1);
        perm[p] = src[i];
    }
}

// ---------------------------------------------------------------------------
__device__ __forceinline__ __half2 load_h2(const float* p, bool relu) {
    float2 v = *(const float2*)p;
    if (relu) { v.x = fmaxf(v.x, 0.0f); v.y = fmaxf(v.y, 0.0f); }
    return __floats2half2_rn(v.x, v.y);
}
__device__ __forceinline__ __half2 load_h2(const __half* p, bool relu) {
    __half2 v = *(const __half2*)p;
    if (relu) v = __hmax2(v, __floats2half2_rn(0.0f, 0.0f));
    return v;
}

// ---------------------------------------------------------------------------
// Tensor-core GEMM: hs(half) = (act(x) @ W) * dinv[row]
template <int FIN, int FOUT, bool RELU, typename TIN>
__global__ void k_gemm_mma(const TIN* __restrict__ x, const float* __restrict__ W,
                           const float* __restrict__ dinv, __half* __restrict__ h, int N) {
    constexpr int KC = FIN / 16;
    constexpr int NT = FOUT / 8;
    constexpr int ASTR = FIN + 8;
    constexpr int BSTR = FOUT + 8;
    __shared__ __half As[128 * ASTR];
    __shared__ __half Bs[FIN * BSTR];
    int tid = threadIdx.x;
    int base = blockIdx.x * 128;

    for (int i = tid; i < FIN * FOUT; i += 256) {
        int r = i / FOUT, cc = i % FOUT;
        Bs[r * BSTR + cc] = __float2half_rn(W[i]);
    }
    constexpr int PAIRS = 128 * FIN / 2;
    for (int p = tid; p < PAIRS; p += 256) {
        int r = p / (FIN / 2), cp = p % (FIN / 2);
        int grow = base + r;
        __half2 hv = (grow < N) ? load_h2(&x[(long long)grow * FIN + cp * 2], RELU)
                                : __floats2half2_rn(0.0f, 0.0f);
        *(__half2*)&As[r * ASTR + cp * 2] = hv;
    }
    __syncthreads();

    int warp = tid >> 5, lane = tid & 31;
    float acc[NT][4];
#pragma unroll
    for (int nt = 0; nt < NT; nt++)
#pragma unroll
        for (int j = 0; j < 4; j++) acc[nt][j] = 0.0f;

    uint32_t a_addr0 = (uint32_t)__cvta_generic_to_shared(
        &As[(warp * 16 + (lane & 15)) * ASTR + (lane >> 4) * 8]);
    uint32_t b_row = (lane & 15);

#pragma unroll
    for (int kc = 0; kc < KC; kc++) {
        uint32_t a0, a1, a2, a3;
        uint32_t aa = a_addr0 + kc * 16 * 2;
        asm volatile("ldmatrix.sync.aligned.m8n8.x4.shared.b16 {%0,%1,%2,%3}, [%4];"
                     : "=r"(a0), "=r"(a1), "=r"(a2), "=r"(a3) : "r"(aa));
#pragma unroll
        for (int nt = 0; nt < NT; nt++) {
            uint32_t b0, b1;
            uint32_t ba = (uint32_t)__cvta_generic_to_shared(
                &Bs[(kc * 16 + b_row) * BSTR + nt * 8]);
            asm volatile("ldmatrix.sync.aligned.m8n8.x2.trans.shared.b16 {%0,%1}, [%2];"
                         : "=r"(b0), "=r"(b1) : "r"(ba));
            asm volatile(
                "mma.sync.aligned.m16n8k16.row.col.f32.f16.f16.f32 "
                "{%0,%1,%2,%3}, {%4,%5,%6,%7}, {%8,%9}, {%0,%1,%2,%3};"
                : "+f"(acc[nt][0]), "+f"(acc[nt][1]), "+f"(acc[nt][2]), "+f"(acc[nt][3])
                : "r"(a0), "r"(a1), "r"(a2), "r"(a3), "r"(b0), "r"(b1));
        }
    }

    int r0 = base + warp * 16 + (lane >> 2);
    int r1 = r0 + 8;
    float d0 = (r0 < N) ? dinv[r0] : 0.0f;
    float d1 = (r1 < N) ? dinv[r1] : 0.0f;
    int colb = (lane & 3) * 2;
#pragma unroll
    for (int nt = 0; nt < NT; nt++) {
        int col = nt * 8 + colb;
        if (r0 < N)
            *(__half2*)&h[(long long)r0 * FOUT + col] =
                __floats2half2_rn(acc[nt][0] * d0, acc[nt][1] * d0);
        if (r1 < N)
            *(__half2*)&h[(long long)r1 * FOUT + col] =
                __floats2half2_rn(acc[nt][2] * d1, acc[nt][3] * d1);
    }
}

// ---------------------------------------------------------------------------
// CSR aggregation: out[d] = half( dinv[d]*(hs[d] + sum hs[src]) + b )
__global__ void k_agg64(const int* __restrict__ start, const int* __restrict__ cnt,
                        const int* __restrict__ perm,
                        const __half* __restrict__ hs, const float* __restrict__ dinv,
                        const float* __restrict__ b, __half* __restrict__ out, int N) {
    int warp = (blockIdx.x * blockDim.x + threadIdx.x) >> 5;
    if (warp >= N) return;
    int lane = threadIdx.x & 31;
    const __half2* H = (const __half2*)hs;
    float2 acc = __half22float2(H[(long long)warp * 32 + lane]);
    int lo = start[warp], hi = lo + cnt[warp];
    for (int base = lo; base < hi; base += 32) {
        int n = min(32, hi - base);
        int s = (lane < n) ? perm[base + lane] : 0;
        for (int j = 0; j < n; j++) {
            int sj = __shfl_sync(0xffffffffu, s, j);
            float2 v = __half22float2(H[(long long)sj * 32 + lane]);
            acc.x += v.x; acc.y += v.y;
        }
    }
    float d = dinv[warp];
    float2 bb = ((const float2*)b)[lane];
    ((__half2*)out)[(long long)warp * 32 + lane] =
        __floats2half2_rn(acc.x * d + bb.x, acc.y * d + bb.y);
}

__global__ void k_agg32(const int* __restrict__ start, const int* __restrict__ cnt,
                        const int* __restrict__ perm,
                        const __half* __restrict__ hs, const float* __restrict__ dinv,
                        const float* __restrict__ b, __half* __restrict__ out, int N) {
    int t = blockIdx.x * blockDim.x + threadIdx.x;
    int node = t >> 4;
    if (node >= N) return;
    int sub = t & 15;
    const __half2* H = (const __half2*)hs;
    float2 acc = __half22float2(H[(long long)node * 16 + sub]);
    int lo = start[node], hi = lo + cnt[node];
    for (int base = lo; base < hi; base += 16) {
        int n = min(16, hi - base);
        int s = (sub < n) ? perm[base + sub] : 0;
        for (int j = 0; j < n; j++) {
            int sj = __shfl_sync(0xffffffffu, s, j, 16);
            float2 v = __half22float2(H[(long long)sj * 16 + sub]);
            acc.x += v.x; acc.y += v.y;
        }
    }
    float d = dinv[node];
    float2 bb = ((const float2*)b)[sub];
    ((__half2*)out)[(long long)node * 16 + sub] =
        __floats2half2_rn(acc.x * d + bb.x, acc.y * d + bb.y);
}

// ---------------------------------------------------------------------------
// Atomic-free pooling over sorted batch; one block per graph, blockDim = F.
template <int F>
__global__ void k_poolg(const __half* __restrict__ x, const int* __restrict__ batch,
                        int N, float* __restrict__ embed, int mxcol, int mncol) {
    int g = blockIdx.x;
    int j = threadIdx.x;
    int lo = 0, hi = N;
    while (lo < hi) { int m = (lo + hi) >> 1; if (batch[m] < g) lo = m + 1; else hi = m; }
    int lo2 = lo, hi2 = N;
    while (lo2 < hi2) { int m = (lo2 + hi2) >> 1; if (batch[m] < g + 1) lo2 = m + 1; else hi2 = m; }
    float mx = 0.0f, sum = 0.0f;
    for (int r = lo; r < lo2; r++) {
        float v = fmaxf(__half2float(x[(long long)r * F + j]), 0.0f);
        mx = fmaxf(mx, v);
        sum += v;
    }
    float n = (float)(lo2 - lo);
    embed[(long long)g * 192 + mxcol + j] = mx;
    embed[(long long)g * 192 + mncol + j] = sum / fmaxf(n, 1.0f);
}

// ---------------------------------------------------------------------------
// Dense head: GPB graphs per block, Wd staged in dynamic smem (~99 KB) so it
// is read NG/GPB times from L2 instead of NG times.
#define GPB 8
__global__ void k_dense2(const float* __restrict__ embed, const float* __restrict__ Wd,
                         const float* __restrict__ bd, const float* __restrict__ Wo,
                         const float* __restrict__ bo, float* __restrict__ out) {
    extern __shared__ float sm[];
    float* Wds = sm;               // 192*128
    float* Wos = Wds + 192 * 128;  // 128
    float* es  = Wos + 128;        // 192
    float* red = es + 192;         // 4
    int tid = threadIdx.x;
    for (int i = tid; i < 192 * 128; i += 128) Wds[i] = Wd[i];
    Wos[tid] = Wo[tid];
    float mybd = bd[tid];
    __syncthreads();

#pragma unroll 1
    for (int gi = 0; gi < GPB; gi++) {
        int g = blockIdx.x * GPB + gi;
        for (int i = tid; i < 192; i += 128) es[i] = embed[(long long)g * 192 + i];
        __syncthreads();
        float a = mybd;
#pragma unroll 8
        for (int k = 0; k < 192; k++) a += es[k] * Wds[k * 128 + tid];
        a = fmaxf(a, 0.0f);
        float v = a * Wos[tid];
#pragma unroll
        for (int o = 16; o > 0; o >>= 1) v += __shfl_down_sync(0xffffffffu, v, o);
        if ((tid & 31) == 0) red[tid >> 5] = v;
        __syncthreads();
        if (tid == 0) out[g] = red[0] + red[1] + red[2] + red[3] + bo[0];
        __syncthreads();
    }
}

// ---------------------------------------------------------------------------
extern "C" void kernel_launch(void* const* d_in, const int* in_sizes, int n_in,
                              void* d_out, int out_size) {
    const float* c       = (const float*)d_in[0];
    const int*   c_edge  = (const int*)d_in[1];
    const int*   c_batch = (const int*)d_in[2];
    const float* s       = (const float*)d_in[3];
    const int*   s_edge  = (const int*)d_in[4];
    const int*   s_batch = (const int*)d_in[5];
    const float* Wc0 = (const float*)d_in[6],  *bc0 = (const float*)d_in[7];
    const float* Wc1 = (const float*)d_in[8],  *bc1 = (const float*)d_in[9];
    const float* Wc2 = (const float*)d_in[10], *bc2 = (const float*)d_in[11];
    const float* Ws0 = (const float*)d_in[12], *bs0 = (const float*)d_in[13];
    const float* Ws1 = (const float*)d_in[14], *bs1 = (const float*)d_in[15];
    const float* Ws2 = (const float*)d_in[16], *bs2 = (const float*)d_in[17];
    const float* Wd  = (const float*)d_in[18], *bd  = (const float*)d_in[19];
    const float* Wo  = (const float*)d_in[20], *bo  = (const float*)d_in[21];

    int Nc = in_sizes[0] / 64;
    int Ec = in_sizes[1] / 2;
    int Ns = in_sizes[3] / 64;
    int Es = in_sizes[4] / 2;

    float* out   = (float*)d_out;
    float* embed = out + NG;  // [NG, 192]

    __half *hs_c, *hB_c, *hs_s, *hB_s;
    float *dinv_c, *dinv_s;
    int *cnt_c, *cnt_s, *start_c, *start_s, *cursor_c, *cursor_s;
    int *perm_c, *perm_s, *tot_c, *tot_s;
    cudaGetSymbolAddress((void**)&hs_c, g_hs_c);
    cudaGetSymbolAddress((void**)&hB_c, g_hB_c);
    cudaGetSymbolAddress((void**)&hs_s, g_hs_s);
    cudaGetSymbolAddress((void**)&hB_s, g_hB_s);
    cudaGetSymbolAddress((void**)&dinv_c, g_dinv_c);
    cudaGetSymbolAddress((void**)&dinv_s, g_dinv_s);
    cudaGetSymbolAddress((void**)&cnt_c, g_cnt_c);
    cudaGetSymbolAddress((void**)&cnt_s, g_cnt_s);
    cudaGetSymbolAddress((void**)&start_c, g_start_c);
    cudaGetSymbolAddress((void**)&start_s, g_start_s);
    cudaGetSymbolAddress((void**)&cursor_c, g_cursor_c);
    cudaGetSymbolAddress((void**)&cursor_s, g_cursor_s);
    cudaGetSymbolAddress((void**)&perm_c, g_perm_c);
    cudaGetSymbolAddress((void**)&perm_s, g_perm_s);
    cudaGetSymbolAddress((void**)&tot_c, g_tot_c);
    cudaGetSymbolAddress((void**)&tot_s, g_tot_s);

    static cudaStream_t s2 = nullptr, s3 = nullptr, s4 = nullptr;
    static cudaEvent_t evF = nullptr, evDc = nullptr, evDs = nullptr;
    static cudaEvent_t evA = nullptr, evB = nullptr, evJ = nullptr;
    static bool tried = false;
    const int HEAD_SMEM = (192 * 128 + 128 + 192 + 4) * 4;
    if (!tried) {
        tried = true;
        bool ok = cudaStreamCreateWithFlags(&s2, cudaStreamNonBlocking) == cudaSuccess &&
                  cudaStreamCreateWithFlags(&s3, cudaStreamNonBlocking) == cudaSuccess &&
                  cudaStreamCreateWithFlags(&s4, cudaStreamNonBlocking) == cudaSuccess;
        if (ok) {
            cudaEventCreateWithFlags(&evF, cudaEventDisableTiming);
            cudaEventCreateWithFlags(&evDc, cudaEventDisableTiming);
            cudaEventCreateWithFlags(&evDs, cudaEventDisableTiming);
            cudaEventCreateWithFlags(&evA, cudaEventDisableTiming);
            cudaEventCreateWithFlags(&evB, cudaEventDisableTiming);
            cudaEventCreateWithFlags(&evJ, cudaEventDisableTiming);
        } else {
            s2 = s3 = s4 = nullptr;
        }
        cudaFuncSetAttribute(k_dense2, cudaFuncAttributeMaxDynamicSharedMemorySize,
                             HEAD_SMEM);
    }
    bool fork = (s2 != nullptr);
    cudaStream_t st0 = 0;
    cudaStream_t stS = fork ? s2 : st0;
    cudaStream_t stA = fork ? s3 : st0;
    cudaStream_t stB = fork ? s4 : st0;

    if (fork) {
        cudaEventRecord(evF, st0);
        cudaStreamWaitEvent(stS, evF, 0);
        cudaStreamWaitEvent(stA, evF, 0);
        cudaStreamWaitEvent(stB, evF, 0);
    }

    const int T = 256;
    const int GS = 1184;

    int mmaBc = (Nc + 127) / 128;
    int aggBc = (Nc * 32 + T - 1) / T;
    int mmaBs = (Ns + 127) / 128;
    int aggBs = (Ns * 16 + T - 1) / T;

    // ================= c branch (F=64) on st0 (+stA for gemm0) =============
    {
        int N = Nc, E = Ec;
        k_zero<<<(N + T - 1) / T, T, 0, st0>>>(cnt_c, tot_c, N);
        k_count<<<GS, T, 0, st0>>>(c_edge + E, E, cnt_c);
        k_offsets<<<(N + T - 1) / T, T, 0, st0>>>(cnt_c, start_c, cursor_c, dinv_c, tot_c, N);
        if (fork) {
            cudaEventRecord(evDc, st0);                 // dinv ready
            cudaStreamWaitEvent(stA, evDc, 0);
            k_gemm_mma<64, 64, false><<<mmaBc, 256, 0, stA>>>(c, Wc0, dinv_c, hs_c, N);
            cudaEventRecord(evA, stA);
        }
        k_build<<<GS, T, 0, st0>>>(c_edge, c_edge + E, cursor_c, perm_c, E);  // overlaps gemm0
        if (fork) cudaStreamWaitEvent(st0, evA, 0);
        else      k_gemm_mma<64, 64, false><<<mmaBc, 256, 0, st0>>>(c, Wc0, dinv_c, hs_c, N);
        k_agg64<<<aggBc, T, 0, st0>>>(start_c, cnt_c, perm_c, hs_c, dinv_c, bc0, hB_c, N);
        k_gemm_mma<64, 64, true><<<mmaBc, 256, 0, st0>>>(hB_c, Wc1, dinv_c, hs_c, N);
        k_agg64<<<aggBc, T, 0, st0>>>(start_c, cnt_c, perm_c, hs_c, dinv_c, bc1, hB_c, N);
        k_gemm_mma<64, 64, true><<<mmaBc, 256, 0, st0>>>(hB_c, Wc2, dinv_c, hs_c, N);
        k_agg64<<<aggBc, T, 0, st0>>>(start_c, cnt_c, perm_c, hs_c, dinv_c, bc2, hB_c, N);
        k_poolg<64><<<NG, 64, 0, st0>>>(hB_c, c_batch, N, embed, 0, 64);
    }

    // ================= s branch (F=32) on stS (+stB for gemm0) =============
    {
        int N = Ns, E = Es;
        k_zero<<<(N + T - 1) / T, T, 0, stS>>>(cnt_s, tot_s, N);
        k_count<<<GS, T, 0, stS>>>(s_edge + E, E, cnt_s);
        k_offsets<<<(N + T - 1) / T, T, 0, stS>>>(cnt_s, start_s, cursor_s, dinv_s, tot_s, N);
        if (fork) {
            cudaEventRecord(evDs, stS);                 // dinv ready
            cudaStreamWaitEvent(stB, evDs, 0);
            k_gemm_mma<64, 32, false><<<mmaBs, 256, 0, stB>>>(s, Ws0, dinv_s, hs_s, N);
            cudaEventRecord(evB, stB);
        }
        k_build<<<GS, T, 0, stS>>>(s_edge, s_edge + E, cursor_s, perm_s, E);  // overlaps gemm0
        if (fork) cudaStreamWaitEvent(stS, evB, 0);
        else      k_gemm_mma<64, 32, false><<<mmaBs, 256, 0, stS>>>(s, Ws0, dinv_s, hs_s, N);
        k_agg32<<<aggBs, T, 0, stS>>>(start_s, cnt_s, perm_s, hs_s, dinv_s, bs0, hB_s, N);
        k_gemm_mma<32, 32, true><<<mmaBs, 256, 0, stS>>>(hB_s, Ws1, dinv_s, hs_s, N);
        k_agg32<<<aggBs, T, 0, stS>>>(start_s, cnt_s, perm_s, hs_s, dinv_s, bs1, hB_s, N);
        k_gemm_mma<32, 32, true><<<mmaBs, 256, 0, stS>>>(hB_s, Ws2, dinv_s, hs_s, N);
        k_agg32<<<aggBs, T, 0, stS>>>(start_s, cnt_s, perm_s, hs_s, dinv_s, bs2, hB_s, N);
        k_poolg<32><<<NG, 32, 0, stS>>>(hB_s, s_batch, N, embed, 128, 160);
    }

    if (fork) {
        cudaEventRecord(evJ, stS);
        cudaStreamWaitEvent(st0, evJ, 0);
    }

    // ================= head =================
    k_dense2<<<NG / GPB, 128, HEAD_SMEM, st0>>>(embed, Wd, bd, Wo, bo, out);
}

// round 12
// speedup vs baseline: 1.1715x; 1.0052x over previous
#include <cuda_runtime.h>
#include <cuda_fp16.h>
#include <cstdint>

#define NG 2048
static const int NMAX = 100000;
static const int EMAX = 1250000;

// Per-branch scratch (device globals — no allocations allowed)
__device__ __align__(16) __half g_hs_c[NMAX * 64];   // gemm out (scaled, fp16)
__device__ __align__(16) __half g_hB_c[NMAX * 64];   // conv out (fp16)
__device__ __align__(16) __half g_hs_s[NMAX * 32];
__device__ __align__(16) __half g_hB_s[NMAX * 32];
__device__ float g_dinv_c[NMAX];
__device__ float g_dinv_s[NMAX];
__device__ int   g_cnt_c[NMAX];
__device__ int   g_cnt_s[NMAX];
__device__ int   g_start_c[NMAX];
__device__ int   g_start_s[NMAX];
__device__ int   g_cursor_c[NMAX];
__device__ int   g_cursor_s[NMAX];
__device__ int   g_perm_c[EMAX];
__device__ int   g_perm_s[EMAX];
__device__ int   g_tot_c;
__device__ int   g_tot_s;

// ---------------------------------------------------------------------------
__global__ void k_zero(int* cnt, int* tot, int n) {
    int i = blockIdx.x * blockDim.x + threadIdx.x;
    if (i < n) cnt[i] = 0;
    if (i == 0) *tot = 0;
}

__global__ void k_count(const int* __restrict__ dst, int E, int* cnt) {
    int stride = gridDim.x * blockDim.x;
    for (int i = blockIdx.x * blockDim.x + threadIdx.x; i < E; i += stride)
        atomicAdd(&cnt[dst[i]], 1);
}

// Warp-aggregated segment assignment + dinv.
__global__ void k_offsets(const int* __restrict__ cnt, int* start, int* cursor,
                          float* dinv, int* tot, int n) {
    int i = blockIdx.x * blockDim.x + threadIdx.x;
    int lane = threadIdx.x & 31;
    int c = (i < n) ? cnt[i] : 0;
    int inc = c;
#pragma unroll
    for (int off = 1; off < 32; off <<= 1) {
        int u = __shfl_up_sync(0xffffffffu, inc, off);
        if (lane >= off) inc += u;
    }
    int wtot = __shfl_sync(0xffffffffu, inc, 31);
    int base = 0;
    if (lane == 31) base = atomicAdd(tot, wtot);
    base = __shfl_sync(0xffffffffu, base, 31);
    if (i < n) {
        int st = base + inc - c;
        start[i] = st;
        cursor[i] = st;
        dinv[i] = rsqrtf(1.0f + (float)c);
    }
}

__global__ void k_build(const int* __restrict__ src, const int* __restrict__ dst,
                        int* cursor, int* perm, int E) {
    int stride = gridDim.x * blockDim.x;
    for (int i = blockIdx.x * blockDim.x + threadIdx.x; i < E; i += stride) {
        int p = atomicAdd(&cursor[dst[i]], 1);
        perm[p] = src[i];
    }
}

// ---------------------------------------------------------------------------
__device__ __forceinline__ __half2 load_h2(const float* p, bool relu) {
    float2 v = *(const float2*)p;
    if (relu) { v.x = fmaxf(v.x, 0.0f); v.y = fmaxf(v.y, 0.0f); }
    return __floats2half2_rn(v.x, v.y);
}
__device__ __forceinline__ __half2 load_h2(const __half* p, bool relu) {
    __half2 v = *(const __half2*)p;
    if (relu) v = __hmax2(v, __floats2half2_rn(0.0f, 0.0f));
    return v;
}

// ---------------------------------------------------------------------------
// Tensor-core GEMM: hs(half) = (act(x) @ W) * dinv[row]
template <int FIN, int FOUT, bool RELU, typename TIN>
__global__ void k_gemm_mma(const TIN* __restrict__ x, const float* __restrict__ W,
                           const float* __restrict__ dinv, __half* __restrict__ h, int N) {
    constexpr int KC = FIN / 16;
    constexpr int NT = FOUT / 8;
    constexpr int ASTR = FIN + 8;
    constexpr int BSTR = FOUT + 8;
    __shared__ __half As[128 * ASTR];
    __shared__ __half Bs[FIN * BSTR];
    int tid = threadIdx.x;
    int base = blockIdx.x * 128;

    for (int i = tid; i < FIN * FOUT; i += 256) {
        int r = i / FOUT, cc = i % FOUT;
        Bs[r * BSTR + cc] = __float2half_rn(W[i]);
    }
    constexpr int PAIRS = 128 * FIN / 2;
    for (int p = tid; p < PAIRS; p += 256) {
        int r = p / (FIN / 2), cp = p % (FIN / 2);
        int grow = base + r;
        __half2 hv = (grow < N) ? load_h2(&x[(long long)grow * FIN + cp * 2], RELU)
                                : __floats2half2_rn(0.0f, 0.0f);
        *(__half2*)&As[r * ASTR + cp * 2] = hv;
    }
    __syncthreads();

    int warp = tid >> 5, lane = tid & 31;
    float acc[NT][4];
#pragma unroll
    for (int nt = 0; nt < NT; nt++)
#pragma unroll
        for (int j = 0; j < 4; j++) acc[nt][j] = 0.0f;

    uint32_t a_addr0 = (uint32_t)__cvta_generic_to_shared(
        &As[(warp * 16 + (lane & 15)) * ASTR + (lane >> 4) * 8]);
    uint32_t b_row = (lane & 15);

#pragma unroll
    for (int kc = 0; kc < KC; kc++) {
        uint32_t a0, a1, a2, a3;
        uint32_t aa = a_addr0 + kc * 16 * 2;
        asm volatile("ldmatrix.sync.aligned.m8n8.x4.shared.b16 {%0,%1,%2,%3}, [%4];"
                     : "=r"(a0), "=r"(a1), "=r"(a2), "=r"(a3) : "r"(aa));
#pragma unroll
        for (int nt = 0; nt < NT; nt++) {
            uint32_t b0, b1;
            uint32_t ba = (uint32_t)__cvta_generic_to_shared(
                &Bs[(kc * 16 + b_row) * BSTR + nt * 8]);
            asm volatile("ldmatrix.sync.aligned.m8n8.x2.trans.shared.b16 {%0,%1}, [%2];"
                         : "=r"(b0), "=r"(b1) : "r"(ba));
            asm volatile(
                "mma.sync.aligned.m16n8k16.row.col.f32.f16.f16.f32 "
                "{%0,%1,%2,%3}, {%4,%5,%6,%7}, {%8,%9}, {%0,%1,%2,%3};"
                : "+f"(acc[nt][0]), "+f"(acc[nt][1]), "+f"(acc[nt][2]), "+f"(acc[nt][3])
                : "r"(a0), "r"(a1), "r"(a2), "r"(a3), "r"(b0), "r"(b1));
        }
    }

    int r0 = base + warp * 16 + (lane >> 2);
    int r1 = r0 + 8;
    float d0 = (r0 < N) ? dinv[r0] : 0.0f;
    float d1 = (r1 < N) ? dinv[r1] : 0.0f;
    int colb = (lane & 3) * 2;
#pragma unroll
    for (int nt = 0; nt < NT; nt++) {
        int col = nt * 8 + colb;
        if (r0 < N)
            *(__half2*)&h[(long long)r0 * FOUT + col] =
                __floats2half2_rn(acc[nt][0] * d0, acc[nt][1] * d0);
        if (r1 < N)
            *(__half2*)&h[(long long)r1 * FOUT + col] =
                __floats2half2_rn(acc[nt][2] * d1, acc[nt][3] * d1);
    }
}

// ---------------------------------------------------------------------------
// CSR aggregation: out[d] = half( dinv[d]*(hs[d] + sum hs[src]) + b )
__global__ void k_agg64(const int* __restrict__ start, const int* __restrict__ cnt,
                        const int* __restrict__ perm,
                        const __half* __restrict__ hs, const float* __restrict__ dinv,
                        const float* __restrict__ b, __half* __restrict__ out, int N) {
    int warp = (blockIdx.x * blockDim.x + threadIdx.x) >> 5;
    if (warp >= N) return;
    int lane = threadIdx.x & 31;
    const __half2* H = (const __half2*)hs;
    float2 acc = __half22float2(H[(long long)warp * 32 + lane]);
    int lo = start[warp], hi = lo + cnt[warp];
    for (int base = lo; base < hi; base += 32) {
        int n = min(32, hi - base);
        int s = (lane < n) ? perm[base + lane] : 0;
        for (int j = 0; j < n; j++) {
            int sj = __shfl_sync(0xffffffffu, s, j);
            float2 v = __half22float2(H[(long long)sj * 32 + lane]);
            acc.x += v.x; acc.y += v.y;
        }
    }
    float d = dinv[warp];
    float2 bb = ((const float2*)b)[lane];
    ((__half2*)out)[(long long)warp * 32 + lane] =
        __floats2half2_rn(acc.x * d + bb.x, acc.y * d + bb.y);
}

__global__ void k_agg32(const int* __restrict__ start, const int* __restrict__ cnt,
                        const int* __restrict__ perm,
                        const __half* __restrict__ hs, const float* __restrict__ dinv,
                        const float* __restrict__ b, __half* __restrict__ out, int N) {
    int t = blockIdx.x * blockDim.x + threadIdx.x;
    int node = t >> 4;
    if (node >= N) return;
    int sub = t & 15;
    const __half2* H = (const __half2*)hs;
    float2 acc = __half22float2(H[(long long)node * 16 + sub]);
    int lo = start[node], hi = lo + cnt[node];
    for (int base = lo; base < hi; base += 16) {
        int n = min(16, hi - base);
        int s = (sub < n) ? perm[base + sub] : 0;
        for (int j = 0; j < n; j++) {
            int sj = __shfl_sync(0xffffffffu, s, j, 16);
            float2 v = __half22float2(H[(long long)sj * 16 + sub]);
            acc.x += v.x; acc.y += v.y;
        }
    }
    float d = dinv[node];
    float2 bb = ((const float2*)b)[sub];
    ((__half2*)out)[(long long)node * 16 + sub] =
        __floats2half2_rn(acc.x * d + bb.x, acc.y * d + bb.y);
}

// ---------------------------------------------------------------------------
// Atomic-free pooling over sorted batch; one block per graph, blockDim = F.
template <int F>
__global__ void k_poolg(const __half* __restrict__ x, const int* __restrict__ batch,
                        int N, float* __restrict__ embed, int mxcol, int mncol) {
    int g = blockIdx.x;
    int j = threadIdx.x;
    int lo = 0, hi = N;
    while (lo < hi) { int m = (lo + hi) >> 1; if (batch[m] < g) lo = m + 1; else hi = m; }
    int lo2 = lo, hi2 = N;
    while (lo2 < hi2) { int m = (lo2 + hi2) >> 1; if (batch[m] < g + 1) lo2 = m + 1; else hi2 = m; }
    float mx = 0.0f, sum = 0.0f;
    for (int r = lo; r < lo2; r++) {
        float v = fmaxf(__half2float(x[(long long)r * F + j]), 0.0f);
        mx = fmaxf(mx, v);
        sum += v;
    }
    float n = (float)(lo2 - lo);
    embed[(long long)g * 192 + mxcol + j] = mx;
    embed[(long long)g * 192 + mncol + j] = sum / fmaxf(n, 1.0f);
}

// ---------------------------------------------------------------------------
// Register-blocked dense head: 8 graphs per block, small smem (6.1 KB).
// Wd is read once per block (8x less L2 traffic); es broadcasts from smem.
#define GPB 8
__global__ void k_dense8(const float* __restrict__ embed, const float* __restrict__ Wd,
                         const float* __restrict__ bd, const float* __restrict__ Wo,
                         const float* __restrict__ bo, float* __restrict__ out) {
    __shared__ float es[GPB][192];
    __shared__ float red[GPB][4];
    int tid = threadIdx.x;  // 128
    int g0 = blockIdx.x * GPB;
    for (int i = tid; i < GPB * 192; i += 128) {
        int g = i / 192, k = i % 192;
        es[g][k] = embed[(long long)(g0 + g) * 192 + k];
    }
    float mybd = bd[tid];
    float wo = Wo[tid];
    __syncthreads();
    float a[GPB];
#pragma unroll
    for (int g = 0; g < GPB; g++) a[g] = mybd;
#pragma unroll 4
    for (int k = 0; k < 192; k++) {
        float w = Wd[k * 128 + tid];
#pragma unroll
        for (int g = 0; g < GPB; g++) a[g] += es[g][k] * w;
    }
#pragma unroll
    for (int g = 0; g < GPB; g++) {
        float v = fmaxf(a[g], 0.0f) * wo;
#pragma unroll
        for (int o = 16; o > 0; o >>= 1) v += __shfl_down_sync(0xffffffffu, v, o);
        if ((tid & 31) == 0) red[g][tid >> 5] = v;
    }
    __syncthreads();
    if (tid < GPB)
        out[g0 + tid] = red[tid][0] + red[tid][1] + red[tid][2] + red[tid][3] + bo[0];
}

// ---------------------------------------------------------------------------
extern "C" void kernel_launch(void* const* d_in, const int* in_sizes, int n_in,
                              void* d_out, int out_size) {
    const float* c       = (const float*)d_in[0];
    const int*   c_edge  = (const int*)d_in[1];
    const int*   c_batch = (const int*)d_in[2];
    const float* s       = (const float*)d_in[3];
    const int*   s_edge  = (const int*)d_in[4];
    const int*   s_batch = (const int*)d_in[5];
    const float* Wc0 = (const float*)d_in[6],  *bc0 = (const float*)d_in[7];
    const float* Wc1 = (const float*)d_in[8],  *bc1 = (const float*)d_in[9];
    const float* Wc2 = (const float*)d_in[10], *bc2 = (const float*)d_in[11];
    const float* Ws0 = (const float*)d_in[12], *bs0 = (const float*)d_in[13];
    const float* Ws1 = (const float*)d_in[14], *bs1 = (const float*)d_in[15];
    const float* Ws2 = (const float*)d_in[16], *bs2 = (const float*)d_in[17];
    const float* Wd  = (const float*)d_in[18], *bd  = (const float*)d_in[19];
    const float* Wo  = (const float*)d_in[20], *bo  = (const float*)d_in[21];

    int Nc = in_sizes[0] / 64;
    int Ec = in_sizes[1] / 2;
    int Ns = in_sizes[3] / 64;
    int Es = in_sizes[4] / 2;

    float* out   = (float*)d_out;
    float* embed = out + NG;  // [NG, 192]

    __half *hs_c, *hB_c, *hs_s, *hB_s;
    float *dinv_c, *dinv_s;
    int *cnt_c, *cnt_s, *start_c, *start_s, *cursor_c, *cursor_s;
    int *perm_c, *perm_s, *tot_c, *tot_s;
    cudaGetSymbolAddress((void**)&hs_c, g_hs_c);
    cudaGetSymbolAddress((void**)&hB_c, g_hB_c);
    cudaGetSymbolAddress((void**)&hs_s, g_hs_s);
    cudaGetSymbolAddress((void**)&hB_s, g_hB_s);
    cudaGetSymbolAddress((void**)&dinv_c, g_dinv_c);
    cudaGetSymbolAddress((void**)&dinv_s, g_dinv_s);
    cudaGetSymbolAddress((void**)&cnt_c, g_cnt_c);
    cudaGetSymbolAddress((void**)&cnt_s, g_cnt_s);
    cudaGetSymbolAddress((void**)&start_c, g_start_c);
    cudaGetSymbolAddress((void**)&start_s, g_start_s);
    cudaGetSymbolAddress((void**)&cursor_c, g_cursor_c);
    cudaGetSymbolAddress((void**)&cursor_s, g_cursor_s);
    cudaGetSymbolAddress((void**)&perm_c, g_perm_c);
    cudaGetSymbolAddress((void**)&perm_s, g_perm_s);
    cudaGetSymbolAddress((void**)&tot_c, g_tot_c);
    cudaGetSymbolAddress((void**)&tot_s, g_tot_s);

    static cudaStream_t s2 = nullptr, s3 = nullptr, s4 = nullptr;
    static cudaEvent_t evF = nullptr, evD = nullptr, evA = nullptr, evB = nullptr, evJ = nullptr;
    static bool tried = false;
    if (!tried) {
        tried = true;
        bool ok = cudaStreamCreateWithFlags(&s2, cudaStreamNonBlocking) == cudaSuccess &&
                  cudaStreamCreateWithFlags(&s3, cudaStreamNonBlocking) == cudaSuccess &&
                  cudaStreamCreateWithFlags(&s4, cudaStreamNonBlocking) == cudaSuccess;
        if (ok) {
            cudaEventCreateWithFlags(&evF, cudaEventDisableTiming);
            cudaEventCreateWithFlags(&evD, cudaEventDisableTiming);
            cudaEventCreateWithFlags(&evA, cudaEventDisableTiming);
            cudaEventCreateWithFlags(&evB, cudaEventDisableTiming);
            cudaEventCreateWithFlags(&evJ, cudaEventDisableTiming);
        } else {
            s2 = s3 = s4 = nullptr;
        }
    }
    bool fork = (s2 != nullptr);
    cudaStream_t st0 = 0;
    cudaStream_t stS = fork ? s2 : st0;
    cudaStream_t stA = fork ? s3 : st0;
    cudaStream_t stB = fork ? s4 : st0;

    if (fork) {
        cudaEventRecord(evF, st0);
        cudaStreamWaitEvent(stS, evF, 0);
        cudaStreamWaitEvent(stA, evF, 0);
        cudaStreamWaitEvent(stB, evF, 0);
    }

    const int T = 256;
    const int GS = 1184;

    // ================= c branch (F=64) =================
    {
        int N = Nc, E = Ec;
        k_zero<<<(N + T - 1) / T, T, 0, st0>>>(cnt_c, tot_c, N);
        k_count<<<GS, T, 0, st0>>>(c_edge + E, E, cnt_c);
        k_offsets<<<(N + T - 1) / T, T, 0, st0>>>(cnt_c, start_c, cursor_c, dinv_c, tot_c, N);
        k_build<<<GS, T, 0, st0>>>(c_edge, c_edge + E, cursor_c, perm_c, E);
        if (fork) {
            cudaEventRecord(evA, st0);
        }
        int mmaB = (N + 127) / 128;
        int aggB = (N * 32 + T - 1) / T;
        if (fork) {
            cudaStreamWaitEvent(stA, evA, 0);
            k_gemm_mma<64, 64, false><<<mmaB, 256, 0, stA>>>(c, Wc0, dinv_c, hs_c, N);
            cudaEventRecord(evA, stA);
            cudaStreamWaitEvent(st0, evA, 0);
        } else {
            k_gemm_mma<64, 64, false><<<mmaB, 256, 0, st0>>>(c, Wc0, dinv_c, hs_c, N);
        }
        k_agg64<<<aggB, T, 0, st0>>>(start_c, cnt_c, perm_c, hs_c, dinv_c, bc0, hB_c, N);
        k_gemm_mma<64, 64, true><<<mmaB, 256, 0, st0>>>(hB_c, Wc1, dinv_c, hs_c, N);
        k_agg64<<<aggB, T, 0, st0>>>(start_c, cnt_c, perm_c, hs_c, dinv_c, bc1, hB_c, N);
        k_gemm_mma<64, 64, true><<<mmaB, 256, 0, st0>>>(hB_c, Wc2, dinv_c, hs_c, N);
        k_agg64<<<aggB, T, 0, st0>>>(start_c, cnt_c, perm_c, hs_c, dinv_c, bc2, hB_c, N);
        k_poolg<64><<<NG, 64, 0, st0>>>(hB_c, c_batch, N, embed, 0, 64);
    }

    // ================= s branch (F=32) =================
    {
        int N = Ns, E = Es;
        k_zero<<<(N + T - 1) / T, T, 0, stS>>>(cnt_s, tot_s, N);
        k_count<<<GS, T, 0, stS>>>(s_edge + E, E, cnt_s);
        k_offsets<<<(N + T - 1) / T, T, 0, stS>>>(cnt_s, start_s, cursor_s, dinv_s, tot_s, N);
        k_build<<<GS, T, 0, stS>>>(s_edge, s_edge + E, cursor_s, perm_s, E);
        int mmaB = (N + 127) / 128;
        int aggB = (N * 16 + T - 1) / T;
        if (fork) {
            cudaEventRecord(evB, stS);
            cudaStreamWaitEvent(stB, evB, 0);
            k_gemm_mma<64, 32, false><<<mmaB, 256, 0, stB>>>(s, Ws0, dinv_s, hs_s, N);
            cudaEventRecord(evB, stB);
            cudaStreamWaitEvent(stS, evB, 0);
        } else {
            k_gemm_mma<64, 32, false><<<mmaB, 256, 0, stS>>>(s, Ws0, dinv_s, hs_s, N);
        }
        k_agg32<<<aggB, T, 0, stS>>>(start_s, cnt_s, perm_s, hs_s, dinv_s, bs0, hB_s, N);
        k_gemm_mma<32, 32, true><<<mmaB, 256, 0, stS>>>(hB_s, Ws1, dinv_s, hs_s, N);
        k_agg32<<<aggB, T, 0, stS>>>(start_s, cnt_s, perm_s, hs_s, dinv_s, bs1, hB_s, N);
        k_gemm_mma<32, 32, true><<<mmaB, 256, 0, stS>>>(hB_s, Ws2, dinv_s, hs_s, N);
        k_agg32<<<aggB, T, 0, stS>>>(start_s, cnt_s, perm_s, hs_s, dinv_s, bs2, hB_s, N);
        k_poolg<32><<<NG, 32, 0, stS>>>(hB_s, s_batch, N, embed, 128, 160);
    }

    if (fork) {
        cudaEventRecord(evJ, stS);
        cudaStreamWaitEvent(st0, evJ, 0);
    }

    // ================= head =================
    k_dense8<<<NG / GPB, 128, 0, st0>>>(embed, Wd, bd, Wo, bo, out);
}